// round 3
// baseline (speedup 1.0000x reference)
#include <cuda_runtime.h>
#include <stdint.h>

#define BATCH 8
#define NBOX 2048
#define NCLS 80
#define ROWF 84          // 4 box + 80 scores
#define OUT_K 200
#define SCORE_TH 0.01f

// Scratch: candidate keys per (b,c): up to 200 packed u64 each.
// key = score_bits<<32 | (262143 - flat)<<11 | n   (flat = c*2048 + sorted_pos)
__device__ unsigned long long g_cand[BATCH * NCLS * OUT_K];

// ---------------------------------------------------------------------------
// Phase 1: one block per (b,c). Sort scores desc (stable), greedy NMS with
// early exit at 200 kept, emit packed candidates.
// ---------------------------------------------------------------------------
__global__ void __launch_bounds__(256) nms_class_kernel(const float* __restrict__ x) {
    extern __shared__ unsigned char smem_raw[];
    unsigned long long* keys = (unsigned long long*)smem_raw;                 // 16384 B
    float4*             box  = (float4*)(smem_raw + NBOX * 8);                // 32768 B
    float*              area = (float*)(smem_raw + NBOX * (8 + 16));          // 8192 B
    unsigned char*      keep = (unsigned char*)(smem_raw + NBOX * (8+16+4));  // 2048 B
    int*                ctrl = (int*)(smem_raw + NBOX * (8+16+4) + NBOX);     // 8 B

    const int bc  = blockIdx.x;
    const int b   = bc / NCLS;
    const int c   = bc % NCLS;
    const int tid = threadIdx.x;

    const float* xb = x + (size_t)b * NBOX * ROWF;

    // Build sort keys: descending score, ties -> lower original index first.
    for (int n = tid; n < NBOX; n += 256) {
        float s = xb[n * ROWF + 4 + c];
        unsigned int sb = __float_as_uint(s);
        keys[n] = ((unsigned long long)sb << 32) | (unsigned long long)(2047 - n);
    }
    __syncthreads();

    // Bitonic sort (descending), 2048 elems.
    for (int k = 2; k <= NBOX; k <<= 1) {
        for (int j = k >> 1; j > 0; j >>= 1) {
            for (int i = tid; i < NBOX; i += 256) {
                int ixj = i ^ j;
                if (ixj > i) {
                    unsigned long long a = keys[i], d = keys[ixj];
                    bool desc = ((i & k) == 0);
                    if (desc ? (a < d) : (a > d)) { keys[i] = d; keys[ixj] = a; }
                }
            }
            __syncthreads();
        }
    }

    // Gather boxes in sorted order; init keep by score threshold.
    for (int jp = tid; jp < NBOX; jp += 256) {
        unsigned long long kk = keys[jp];
        int n = 2047 - (int)(kk & 0x7FFULL);
        float4 bx = *reinterpret_cast<const float4*>(xb + n * ROWF);  // 336B stride, 16B aligned
        box[jp]  = bx;
        area[jp] = (bx.z - bx.x) * (bx.w - bx.y);
        float s  = __uint_as_float((unsigned int)(kk >> 32));
        keep[jp] = (s > SCORE_TH) ? 1 : 0;
    }
    unsigned long long* cand = g_cand + (size_t)bc * OUT_K;
    for (int t = tid; t < OUT_K; t += 256) cand[t] = 0ULL;  // sentinel = -inf slot
    if (tid == 0) ctrl[0] = 0;
    __syncthreads();

    // Greedy NMS: serial over heads, parallel suppression. Early exit at 200.
    int i = 0;
    int count = 0;
    while (count < OUT_K) {
        // warp 0: ballot-scan for next kept position >= i
        if (tid < 32) {
            int found = NBOX;
            int p = i;
            while (p < NBOX) {
                int q = p + tid;
                unsigned int m = __ballot_sync(0xFFFFFFFFu, (q < NBOX) && keep[q]);
                if (m) { found = p + __ffs(m) - 1; break; }
                p += 32;
            }
            if (tid == 0) ctrl[0] = found;
        }
        __syncthreads();
        int head = ctrl[0];
        if (head >= NBOX) break;

        if (tid == 0) {
            unsigned long long kk = keys[head];
            unsigned int sb   = (unsigned int)(kk >> 32);
            unsigned int n    = (unsigned int)(2047 - (int)(kk & 0x7FFULL));
            unsigned int flat = (unsigned int)(c * NBOX + head);
            unsigned int invf = 262143u - flat;   // 18 bits; lower flat sorts first on ties
            cand[count] = ((unsigned long long)sb << 32)
                        | ((unsigned long long)invf << 11)
                        | (unsigned long long)n;
        }
        count++;

        if (count < OUT_K) {   // 200th head's suppression cannot change output
            float4 hb = box[head];
            float  ha = area[head];
            for (int j2 = head + 1 + tid; j2 < NBOX; j2 += 256) {
                if (keep[j2]) {
                    float4 bb = box[j2];
                    float lx = fmaxf(hb.x, bb.x);
                    float ly = fmaxf(hb.y, bb.y);
                    float rx = fminf(hb.z, bb.z);
                    float ry = fminf(hb.w, bb.w);
                    float w  = fmaxf(rx - lx, 0.0f);
                    float h  = fmaxf(ry - ly, 0.0f);
                    float inter = w * h;
                    float uni   = ha + area[j2] - inter;
                    if (inter > 0.5f * fmaxf(uni, 1e-8f)) keep[j2] = 0;
                }
            }
        }
        i = head + 1;
        __syncthreads();
    }
}

// ---------------------------------------------------------------------------
// Phase 2: one block per batch. Top-200 of 16000 candidate keys via bitonic
// sort of 16384 u64 in smem, then decode + clip + write output rows.
// ---------------------------------------------------------------------------
__global__ void __launch_bounds__(1024) topk_kernel(const float* __restrict__ x,
                                                    float* __restrict__ out) {
    extern __shared__ unsigned long long sk[];
    const int b   = blockIdx.x;
    const int tid = threadIdx.x;
    const int M   = 16384;
    const int NC  = NCLS * OUT_K;  // 16000

    const unsigned long long* cand = g_cand + (size_t)b * NC;
    for (int t = tid; t < M; t += 1024) sk[t] = (t < NC) ? cand[t] : 0ULL;
    __syncthreads();

    for (int k = 2; k <= M; k <<= 1) {
        for (int j = k >> 1; j > 0; j >>= 1) {
            for (int i = tid; i < M; i += 1024) {
                int ixj = i ^ j;
                if (ixj > i) {
                    unsigned long long a = sk[i], d = sk[ixj];
                    bool desc = ((i & k) == 0);
                    if (desc ? (a < d) : (a > d)) { sk[i] = d; sk[ixj] = a; }
                }
            }
            __syncthreads();
        }
    }

    if (tid < OUT_K) {
        unsigned long long kk = sk[tid];
        float* o = out + ((size_t)b * OUT_K + tid) * 6;
        if (kk == 0ULL) {
            o[0] = 0.f; o[1] = 0.f; o[2] = 0.f; o[3] = 0.f; o[4] = 0.f; o[5] = 0.f;
        } else {
            float score = __uint_as_float((unsigned int)(kk >> 32));
            unsigned int invf = (unsigned int)((kk >> 11) & 0x3FFFFULL);
            unsigned int flat = 262143u - invf;
            int cls = (int)(flat >> 11);           // N = 2048 = 2^11
            int n   = (int)(kk & 0x7FFULL);
            const float* xb = x + ((size_t)b * NBOX + n) * ROWF;
            o[0] = (float)cls;
            o[1] = score;
            o[2] = fminf(fmaxf(xb[0], 0.0f), 1.0f);
            o[3] = fminf(fmaxf(xb[1], 0.0f), 1.0f);
            o[4] = fminf(fmaxf(xb[2], 0.0f), 1.0f);
            o[5] = fminf(fmaxf(xb[3], 0.0f), 1.0f);
        }
    }
}

// ---------------------------------------------------------------------------
extern "C" void kernel_launch(void* const* d_in, const int* in_sizes, int n_in,
                              void* d_out, int out_size) {
    const float* x = (const float*)d_in[0];
    float* out = (float*)d_out;

    const int smem1 = NBOX * (8 + 16 + 4) + NBOX + 16;   // 59408 B
    const int smem2 = 16384 * 8;                          // 131072 B
    cudaFuncSetAttribute(nms_class_kernel, cudaFuncAttributeMaxDynamicSharedMemorySize, smem1);
    cudaFuncSetAttribute(topk_kernel,      cudaFuncAttributeMaxDynamicSharedMemorySize, smem2);

    nms_class_kernel<<<BATCH * NCLS, 256, smem1>>>(x);
    topk_kernel<<<BATCH, 1024, smem2>>>(x, out);
}